// round 2
// baseline (speedup 1.0000x reference)
#include <cuda_runtime.h>
#include <cstdint>
#include <math.h>

// Problem constants
#define G  8
#define T  4096
#define H  1024
#define E  32
#define C  64
#define GT (G*T)                       // 32768 tokens
#define GTEC ((size_t)G*(size_t)T*(size_t)E*(size_t)C)   // 67,108,864

// GEMM tiling
#define MTILE 256
#define KTILE 16
#define XP    257                      // padded xs row (conflict-free LDS)
#define GEMM_BLOCKS (GT/MTILE)         // 128
#define NTHREADS 256
#define NB_K1 1184                     // 148 SMs * 8

// memset work-stealing: 536,870,912 B / 16 B = 33,554,432 uint4
#define CHUNK_U4  8192                 // 128 KB per chunk
#define NCHUNKS   (33554432/CHUNK_U4)  // 4096

// Scratch (device globals; no allocations allowed)
__device__ float g_probs[G*E*T];       // probs transposed [g][e][t], 4 MB
__device__ float g_zpart[GEMM_BLOCKS];
__device__ unsigned int g_ctr;         // memset chunk counter (reset by k2)

// ---------------------------------------------------------------------------
// work-stealing zero fill
// ---------------------------------------------------------------------------
__device__ __forceinline__ void steal_zero(float* __restrict__ out, int tid)
{
    uint4 z; z.x = 0u; z.y = 0u; z.z = 0u; z.w = 0u;
    uint4* o4 = reinterpret_cast<uint4*>(out);
    __shared__ unsigned int chunk_sh;
    for (;;) {
        if (tid == 0) chunk_sh = atomicAdd(&g_ctr, 1u);
        __syncthreads();
        unsigned int c = chunk_sh;
        __syncthreads();
        if (c >= NCHUNKS) return;
        size_t base = (size_t)c * CHUNK_U4 + tid;
#pragma unroll
        for (int j = 0; j < CHUNK_U4 / NTHREADS; j++)     // 32 STG.128
            o4[base + (size_t)j * NTHREADS] = z;
    }
}

// ---------------------------------------------------------------------------
// Kernel 1: blocks [0,128) = GEMM+softmax then join memset; rest memset only.
// ---------------------------------------------------------------------------
__global__ __launch_bounds__(NTHREADS)
void router_k1(const float* __restrict__ x,   // [G,T,H]
               const float* __restrict__ Wm,  // [H,E]
               const float* __restrict__ bv,  // [E]
               float* __restrict__ out)
{
    const int bid = blockIdx.x;
    const int tid = threadIdx.x;

    if (bid >= GEMM_BLOCKS) { steal_zero(out, tid); return; }

    __shared__ __align__(16) float xs[KTILE * XP];
    __shared__ __align__(16) float ws[KTILE * E];
    __shared__ float zred[NTHREADS];

    const int gtBase = bid * MTILE;

    unsigned long long acc[16];
#pragma unroll
    for (int i = 0; i < 16; i++) acc[i] = 0ull;

    for (int kc = 0; kc < H / KTILE; kc++) {
#pragma unroll
        for (int i = tid; i < KTILE * E; i += NTHREADS)
            ws[i] = Wm[kc * KTILE * E + i];

#pragma unroll
        for (int r = 0; r < (MTILE * KTILE / 4) / NTHREADS; r++) {
            int s  = tid + r * NTHREADS;
            int tl = s >> 2;
            int k4 = s & 3;
            const float4 v = *reinterpret_cast<const float4*>(
                x + (size_t)(gtBase + tl) * H + kc * KTILE + k4 * 4);
            xs[(k4 * 4 + 0) * XP + tl] = v.x;
            xs[(k4 * 4 + 1) * XP + tl] = v.y;
            xs[(k4 * 4 + 2) * XP + tl] = v.z;
            xs[(k4 * 4 + 3) * XP + tl] = v.w;
        }
        __syncthreads();

#pragma unroll
        for (int kk = 0; kk < KTILE; kk++) {
            const float xv = xs[kk * XP + tid];
            unsigned long long xx;
            asm("mov.b64 %0, {%1,%1};" : "=l"(xx) : "r"(__float_as_uint(xv)));
            const ulonglong2* wr =
                reinterpret_cast<const ulonglong2*>(ws + kk * E);
#pragma unroll
            for (int q = 0; q < 8; q++) {
                ulonglong2 wp = wr[q];
                asm("fma.rn.f32x2 %0, %1, %2, %0;"
                    : "+l"(acc[2*q])   : "l"(xx), "l"(wp.x));
                asm("fma.rn.f32x2 %0, %1, %2, %0;"
                    : "+l"(acc[2*q+1]) : "l"(xx), "l"(wp.y));
            }
        }
        __syncthreads();
    }

    float l[E];
#pragma unroll
    for (int i = 0; i < 16; i++) {
        float2 f = *reinterpret_cast<float2*>(&acc[i]);
        l[2*i]   = f.x;
        l[2*i+1] = f.y;
    }
#pragma unroll
    for (int e = 0; e < E; e++) l[e] += __ldg(&bv[e]);

    float m = l[0];
#pragma unroll
    for (int e = 1; e < E; e++) m = fmaxf(m, l[e]);
    float s = 0.f;
#pragma unroll
    for (int e = 0; e < E; e++) { l[e] = expf(l[e] - m); s += l[e]; }
    const float inv = 1.f / s;

    const int token = gtBase + tid;
    const int g  = token >> 12;
    const int tt = token & (T - 1);
    float* pr = g_probs + (size_t)g * E * T + tt;
#pragma unroll
    for (int e = 0; e < E; e++) pr[(size_t)e * T] = l[e] * inv;

    const float lse = m + logf(s);
    zred[tid] = lse * lse;
    __syncthreads();
    for (int st = NTHREADS / 2; st > 0; st >>= 1) {
        if (tid < st) zred[tid] += zred[tid + st];
        __syncthreads();
    }
    if (tid == 0) g_zpart[bid] = zred[0];
    __syncthreads();

    steal_zero(out, tid);          // join the zero-fill
}

// ---------------------------------------------------------------------------
// Kernel 2: radix-select top-64 per (g,e) row + bitonic rank sort + scatter.
// Key = (valbits << 12) | (4095 - t): descending key order == descending
// value, ascending token index on ties (matches jax.lax.top_k).
// ---------------------------------------------------------------------------
#define NBINS 8192
#define CAP   1024

__global__ __launch_bounds__(NTHREADS)
void router_k2(float* __restrict__ out)
{
    const int bid = blockIdx.x;
    const int tid = threadIdx.x;

    if (bid == G * E) {
        if (tid == 0) {
            float s = 0.f;
            for (int i = 0; i < GEMM_BLOCKS; i++) s += g_zpart[i];
            out[2 * GTEC] = s / (float)GT;
            g_ctr = 0u;                       // reset for next replay
        }
        return;
    }

    __shared__ int hist[NBINS];
    __shared__ int suf[NTHREADS];
    __shared__ unsigned long long list[CAP];
    __shared__ int Bsh, cntSh;

    float* combine  = out;
    float* dispatch = out + GTEC;

    const int g = bid >> 5;
    const int e = bid & (E - 1);
    const float* row = g_probs + (size_t)(g * E + e) * T;

    unsigned int uv[16];
#pragma unroll
    for (int j = 0; j < 16; j++)
        uv[j] = __float_as_uint(row[tid + j * NTHREADS]);

#pragma unroll
    for (int i = tid; i < NBINS; i += NTHREADS) hist[i] = 0;
    if (tid == 0) cntSh = 0;
    __syncthreads();

#pragma unroll
    for (int j = 0; j < 16; j++)
        atomicAdd(&hist[uv[j] >> 17], 1);
    __syncthreads();

    // per-thread chunk sums (32 bins each), then inclusive suffix scan
    {
        int s = 0;
#pragma unroll
        for (int b = 0; b < 32; b++) s += hist[tid * 32 + b];
        suf[tid] = s;
    }
    __syncthreads();
    for (int off = 1; off < NTHREADS; off <<= 1) {
        int t = (tid + off < NTHREADS) ? suf[tid + off] : 0;
        __syncthreads();
        suf[tid] += t;
        __syncthreads();
    }
    // locate chunk containing the 64th largest, then scan its bins
    {
        int above = (tid + 1 < NTHREADS) ? suf[tid + 1] : 0;
        if (suf[tid] >= C && above < C) {
            int run = above;
            for (int b = tid * 32 + 31; b >= tid * 32; b--) {
                run += hist[b];
                if (run >= C) { Bsh = b; break; }
            }
        }
    }
    __syncthreads();
    const unsigned int B = (unsigned int)Bsh;

    // collect candidates (bin >= B)
#pragma unroll
    for (int j = 0; j < 16; j++) {
        if ((uv[j] >> 17) >= B) {
            int p = atomicAdd(&cntSh, 1);
            if (p < CAP) {
                int t = tid + j * NTHREADS;
                list[p] = ((unsigned long long)uv[j] << 12)
                          | (unsigned long long)(4095 - t);
            }
        }
    }
    __syncthreads();

    int cnt = cntSh; if (cnt > CAP) cnt = CAP;
    int n = 64; while (n < cnt) n <<= 1;
    for (int i = cnt + tid; i < n; i += NTHREADS) list[i] = 0ull;
    __syncthreads();

    // bitonic sort descending
    for (int k = 2; k <= n; k <<= 1) {
        for (int j = k >> 1; j > 0; j >>= 1) {
            for (int i = tid; i < n; i += NTHREADS) {
                int l2 = i ^ j;
                if (l2 > i) {
                    unsigned long long a = list[i], b = list[l2];
                    bool up = ((i & k) == 0);
                    if (up ? (a < b) : (a > b)) { list[i] = b; list[l2] = a; }
                }
            }
            __syncthreads();
        }
    }

    // emit ranks 0..63
    if (tid < C) {
        unsigned long long key = list[tid];
        int t = 4095 - (int)(key & 0xFFFull);
        float val = __uint_as_float((unsigned int)(key >> 12));
        const size_t off = (((size_t)(g * T + t)) * E + e) * C + tid;
        combine[off]  = val;
        dispatch[off] = 1.0f;
    }
}

__global__ void nop_k() {}

// ---------------------------------------------------------------------------
extern "C" void kernel_launch(void* const* d_in, const int* in_sizes, int n_in,
                              void* d_out, int out_size)
{
    const float* x  = (const float*)d_in[0];
    const float* Wm = (const float*)d_in[1];
    const float* bv = (const float*)d_in[2];
    float* out = (float*)d_out;

    router_k1<<<NB_K1, NTHREADS>>>(x, Wm, bv, out);
    router_k2<<<G * E + 1, NTHREADS>>>(out);
    // pad to 5 launches so ncu (-s 5 -c 1) profiles router_k1 next round
    nop_k<<<1, 32>>>();
    nop_k<<<1, 32>>>();
    nop_k<<<1, 32>>>();
}

// round 3
// speedup vs baseline: 1.7097x; 1.7097x over previous
#include <cuda_runtime.h>
#include <cstdint>
#include <math.h>

// Problem constants
#define G  8
#define T  4096
#define H  1024
#define E  32
#define C  64
#define GT (G*T)                       // 32768 tokens
#define GTEC ((size_t)G*(size_t)T*(size_t)E*(size_t)C)   // 67,108,864

// GEMM tiling
#define MTILE 256
#define KTILE 32
#define NKC   (H/KTILE)                // 32 k-chunks
#define XP    257                      // padded xs row (conflict-free LDS)
#define GEMM_BLOCKS (GT/MTILE)         // 128
#define ZERO_BLOCKS 2048
#define NTHREADS 256

// Scratch (device globals; no allocations allowed)
__device__ float g_probs[G*E*T];       // probs transposed [g][e][t], 4 MB
__device__ float g_zpart[GEMM_BLOCKS];

// ---------------------------------------------------------------------------
// Kernel 1: blocks [0,128) = double-buffered GEMM + softmax + z partials;
//           blocks [128, 128+2048) = static grid-stride zero fill of out.
// ---------------------------------------------------------------------------
__global__ __launch_bounds__(NTHREADS)
void router_k1(const float* __restrict__ x,   // [G,T,H]
               const float* __restrict__ Wm,  // [H,E]
               const float* __restrict__ bv,  // [E]
               float* __restrict__ out)
{
    const int bid = blockIdx.x;
    const int tid = threadIdx.x;

    if (bid >= GEMM_BLOCKS) {
        // ---- zero-fill path (no barriers, max MLP) ----
        uint4 z; z.x = 0u; z.y = 0u; z.z = 0u; z.w = 0u;
        uint4* o4 = reinterpret_cast<uint4*>(out);
        const size_t n4 = (2*GTEC) / 4;                    // 33,554,432
        size_t i = (size_t)(bid - GEMM_BLOCKS) * NTHREADS + tid;
        const size_t stride = (size_t)ZERO_BLOCKS * NTHREADS;
        for (; i < n4; i += stride) o4[i] = z;
        return;
    }

    // ---- GEMM path: tokens [bid*256, bid*256+256), all 32 experts ----
    __shared__ __align__(16) float xs[KTILE * XP];   // x tile transposed [k][t]
    __shared__ __align__(16) float ws[KTILE * E];    // W tile [k][e]
    __shared__ float zred[NTHREADS];

    const int gtBase = bid * MTILE;
    const float* xbase = x + (size_t)gtBase * H;

    unsigned long long acc[16];
#pragma unroll
    for (int i = 0; i < 16; i++) acc[i] = 0ull;

    // prefetch registers: 8 float4 of x + 1 float4 of W per thread
    float4 pfx[8];
    float4 pfw;

    // thread -> (token, k-quad) mapping for x loads:
    //   s = r*256 + tid ; tl = s>>3 ; k4 = s&7  (coalesced 128B per token)
#pragma unroll
    for (int r = 0; r < 8; r++) {
        int s  = r * NTHREADS + tid;
        int tl = s >> 3;
        int k4 = s & 7;
        pfx[r] = *reinterpret_cast<const float4*>(xbase + (size_t)tl * H + k4 * 4);
    }
    pfw = *reinterpret_cast<const float4*>(Wm + tid * 4);

    for (int kc = 0; kc < NKC; kc++) {
        __syncthreads();   // previous compute done; smem reusable
        // store prefetched tiles to smem
#pragma unroll
        for (int r = 0; r < 8; r++) {
            int s  = r * NTHREADS + tid;
            int tl = s >> 3;
            int k4 = s & 7;
            xs[(k4 * 4 + 0) * XP + tl] = pfx[r].x;
            xs[(k4 * 4 + 1) * XP + tl] = pfx[r].y;
            xs[(k4 * 4 + 2) * XP + tl] = pfx[r].z;
            xs[(k4 * 4 + 3) * XP + tl] = pfx[r].w;
        }
        *reinterpret_cast<float4*>(ws + tid * 4) = pfw;
        __syncthreads();

        // issue next tile's loads (overlap with compute below)
        if (kc + 1 < NKC) {
            const float* xn = xbase + (kc + 1) * KTILE;
#pragma unroll
            for (int r = 0; r < 8; r++) {
                int s  = r * NTHREADS + tid;
                int tl = s >> 3;
                int k4 = s & 7;
                pfx[r] = *reinterpret_cast<const float4*>(xn + (size_t)tl * H + k4 * 4);
            }
            pfw = *reinterpret_cast<const float4*>(Wm + (kc + 1) * KTILE * E + tid * 4);
        }

        // compute: 32 k-steps, 32 experts as 16 packed f32x2
#pragma unroll
        for (int kk = 0; kk < KTILE; kk++) {
            const float xv = xs[kk * XP + tid];
            unsigned long long xx;
            asm("mov.b64 %0, {%1,%1};" : "=l"(xx) : "r"(__float_as_uint(xv)));
            const ulonglong2* wr = reinterpret_cast<const ulonglong2*>(ws + kk * E);
#pragma unroll
            for (int q = 0; q < 8; q++) {
                ulonglong2 wp = wr[q];
                asm("fma.rn.f32x2 %0, %1, %2, %0;"
                    : "+l"(acc[2*q])   : "l"(xx), "l"(wp.x));
                asm("fma.rn.f32x2 %0, %1, %2, %0;"
                    : "+l"(acc[2*q+1]) : "l"(xx), "l"(wp.y));
            }
        }
    }

    // ---- epilogue: bias, softmax, transposed prob write, z partial ----
    float l[E];
#pragma unroll
    for (int i = 0; i < 16; i++) {
        float2 f = *reinterpret_cast<float2*>(&acc[i]);
        l[2*i]   = f.x;
        l[2*i+1] = f.y;
    }
#pragma unroll
    for (int e = 0; e < E; e++) l[e] += __ldg(&bv[e]);

    float m = l[0];
#pragma unroll
    for (int e = 1; e < E; e++) m = fmaxf(m, l[e]);
    float s = 0.f;
#pragma unroll
    for (int e = 0; e < E; e++) { l[e] = expf(l[e] - m); s += l[e]; }
    const float inv = 1.f / s;

    const int token = gtBase + tid;
    const int g  = token >> 12;
    const int tt = token & (T - 1);
    float* pr = g_probs + (size_t)g * E * T + tt;
#pragma unroll
    for (int e = 0; e < E; e++) pr[(size_t)e * T] = l[e] * inv;

    const float lse = m + logf(s);
    zred[tid] = lse * lse;
    __syncthreads();
    for (int st = NTHREADS / 2; st > 0; st >>= 1) {
        if (tid < st) zred[tid] += zred[tid + st];
        __syncthreads();
    }
    if (tid == 0) g_zpart[bid] = zred[0];
}

// ---------------------------------------------------------------------------
// Kernel 2: per-(g,e) iterative top-C over T tokens, scattering directly.
// Tie-break matches jax.lax.top_k: equal value -> lower token index first.
// Block 256 finalizes z-loss in deterministic order.
// ---------------------------------------------------------------------------
__global__ __launch_bounds__(NTHREADS)
void router_k2(float* __restrict__ out)
{
    const int bid = blockIdx.x;
    const int tid = threadIdx.x;

    if (bid == G * E) {
        if (tid == 0) {
            float s = 0.f;
            for (int i = 0; i < GEMM_BLOCKS; i++) s += g_zpart[i];
            out[2 * GTEC] = s / (float)GT;
        }
        return;
    }

    float* combine  = out;
    float* dispatch = out + GTEC;

    const int g = bid >> 5;
    const int e = bid & (E - 1);
    const float* row = g_probs + (size_t)(g * E + e) * T;

    // each thread owns 16 strided values: token t = j*256 + tid
    float v[16];
#pragma unroll
    for (int j = 0; j < 16; j++) v[j] = row[tid + j * NTHREADS];

    // local best (ascending j => ascending t; strict > keeps lowest t on ties)
    float bvv = -INFINITY; int bt = tid;
#pragma unroll
    for (int j = 0; j < 16; j++)
        if (v[j] > bvv) { bvv = v[j]; bt = j * NTHREADS + tid; }

    __shared__ float swv[8];
    __shared__ int   swt[8];
    __shared__ int   wint;

    const int lane = tid & 31;
    const int wrp  = tid >> 5;

    for (int c = 0; c < C; c++) {
        float rv = bvv; int rt = bt;
#pragma unroll
        for (int off = 16; off; off >>= 1) {
            float ov = __shfl_xor_sync(0xffffffffu, rv, off);
            int   oi = __shfl_xor_sync(0xffffffffu, rt, off);
            if (ov > rv || (ov == rv && oi < rt)) { rv = ov; rt = oi; }
        }
        if (lane == 0) { swv[wrp] = rv; swt[wrp] = rt; }
        __syncthreads();
        if (tid == 0) {
            float Rv = swv[0]; int Rt = swt[0];
            for (int w = 1; w < 8; w++)
                if (swv[w] > Rv || (swv[w] == Rv && swt[w] < Rt)) {
                    Rv = swv[w]; Rt = swt[w];
                }
            wint = Rt;
            const size_t off = (((size_t)(g * T + Rt)) * E + e) * C + c;
            combine[off]  = Rv;
            dispatch[off] = 1.0f;
        }
        __syncthreads();
        const int wt = wint;
        if ((wt & (NTHREADS - 1)) == tid) {
            v[wt >> 8] = -INFINITY;
            bvv = -INFINITY; bt = tid;
#pragma unroll
            for (int j = 0; j < 16; j++)
                if (v[j] > bvv) { bvv = v[j]; bt = j * NTHREADS + tid; }
        }
    }
}

// ---------------------------------------------------------------------------
extern "C" void kernel_launch(void* const* d_in, const int* in_sizes, int n_in,
                              void* d_out, int out_size)
{
    const float* x  = (const float*)d_in[0];
    const float* Wm = (const float*)d_in[1];
    const float* bv = (const float*)d_in[2];
    float* out = (float*)d_out;

    router_k1<<<GEMM_BLOCKS + ZERO_BLOCKS, NTHREADS>>>(x, Wm, bv, out);
    router_k2<<<G * E + 1, NTHREADS>>>(out);
}

// round 4
// speedup vs baseline: 1.8150x; 1.0616x over previous
#include <cuda_runtime.h>
#include <cstdint>
#include <math.h>

// Problem constants
#define G  8
#define T  4096
#define H  1024
#define E  32
#define C  64
#define GT (G*T)                       // 32768 tokens
#define GTEC ((size_t)G*(size_t)T*(size_t)E*(size_t)C)   // 67,108,864

// GEMM tiling
#define MTILE 256
#define KTILE 32
#define NKC   (H/KTILE)                // 32 k-chunks
#define XP    257                      // padded xs row (conflict-free LDS)
#define GEMM_BLOCKS (GT/MTILE)         // 128
#define NTHREADS 256

#define SEL_BLOCKS  (G*E)              // 256
#define ZERO_BLOCKS 2048

// Scratch (device globals; no allocations allowed)
__device__ float g_probs[G*E*T];       // probs transposed [g][e][t], 4 MB
__device__ float g_zpart[GEMM_BLOCKS];
__device__ float g_topv[G*E*C];        // top-64 values per (g,e)
__device__ int   g_topt[G*E*C];        // top-64 token ids per (g,e)

// ---------------------------------------------------------------------------
// Kernel A: double-buffered router GEMM + softmax + z partials (128 blocks).
// Runs with NO concurrent write storm -> clean read latency.
// ---------------------------------------------------------------------------
__global__ __launch_bounds__(NTHREADS)
void router_gemm(const float* __restrict__ x,   // [G,T,H]
                 const float* __restrict__ Wm,  // [H,E]
                 const float* __restrict__ bv)  // [E]
{
    const int bid = blockIdx.x;
    const int tid = threadIdx.x;

    __shared__ __align__(16) float xs[KTILE * XP];
    __shared__ __align__(16) float ws[KTILE * E];
    __shared__ float zred[NTHREADS];

    const int gtBase = bid * MTILE;
    const float* xbase = x + (size_t)gtBase * H;

    unsigned long long acc[16];
#pragma unroll
    for (int i = 0; i < 16; i++) acc[i] = 0ull;

    float4 pfx[8];
    float4 pfw;
#pragma unroll
    for (int r = 0; r < 8; r++) {
        int s  = r * NTHREADS + tid;
        int tl = s >> 3;
        int k4 = s & 7;
        pfx[r] = *reinterpret_cast<const float4*>(xbase + (size_t)tl * H + k4 * 4);
    }
    pfw = *reinterpret_cast<const float4*>(Wm + tid * 4);

    for (int kc = 0; kc < NKC; kc++) {
        __syncthreads();
#pragma unroll
        for (int r = 0; r < 8; r++) {
            int s  = r * NTHREADS + tid;
            int tl = s >> 3;
            int k4 = s & 7;
            xs[(k4 * 4 + 0) * XP + tl] = pfx[r].x;
            xs[(k4 * 4 + 1) * XP + tl] = pfx[r].y;
            xs[(k4 * 4 + 2) * XP + tl] = pfx[r].z;
            xs[(k4 * 4 + 3) * XP + tl] = pfx[r].w;
        }
        *reinterpret_cast<float4*>(ws + tid * 4) = pfw;
        __syncthreads();

        if (kc + 1 < NKC) {
            const float* xn = xbase + (kc + 1) * KTILE;
#pragma unroll
            for (int r = 0; r < 8; r++) {
                int s  = r * NTHREADS + tid;
                int tl = s >> 3;
                int k4 = s & 7;
                pfx[r] = *reinterpret_cast<const float4*>(xn + (size_t)tl * H + k4 * 4);
            }
            pfw = *reinterpret_cast<const float4*>(Wm + (kc + 1) * KTILE * E + tid * 4);
        }

#pragma unroll
        for (int kk = 0; kk < KTILE; kk++) {
            const float xv = xs[kk * XP + tid];
            unsigned long long xx;
            asm("mov.b64 %0, {%1,%1};" : "=l"(xx) : "r"(__float_as_uint(xv)));
            const ulonglong2* wr = reinterpret_cast<const ulonglong2*>(ws + kk * E);
#pragma unroll
            for (int q = 0; q < 8; q++) {
                ulonglong2 wp = wr[q];
                asm("fma.rn.f32x2 %0, %1, %2, %0;"
                    : "+l"(acc[2*q])   : "l"(xx), "l"(wp.x));
                asm("fma.rn.f32x2 %0, %1, %2, %0;"
                    : "+l"(acc[2*q+1]) : "l"(xx), "l"(wp.y));
            }
        }
    }

    float l[E];
#pragma unroll
    for (int i = 0; i < 16; i++) {
        float2 f = *reinterpret_cast<float2*>(&acc[i]);
        l[2*i]   = f.x;
        l[2*i+1] = f.y;
    }
#pragma unroll
    for (int e = 0; e < E; e++) l[e] += __ldg(&bv[e]);

    float m = l[0];
#pragma unroll
    for (int e = 1; e < E; e++) m = fmaxf(m, l[e]);
    float s = 0.f;
#pragma unroll
    for (int e = 0; e < E; e++) { l[e] = expf(l[e] - m); s += l[e]; }
    const float inv = 1.f / s;

    const int token = gtBase + tid;
    const int g  = token >> 12;
    const int tt = token & (T - 1);
    float* pr = g_probs + (size_t)g * E * T + tt;
#pragma unroll
    for (int e = 0; e < E; e++) pr[(size_t)e * T] = l[e] * inv;

    const float lse = m + logf(s);
    zred[tid] = lse * lse;
    __syncthreads();
    for (int st = NTHREADS / 2; st > 0; st >>= 1) {
        if (tid < st) zred[tid] += zred[tid + st];
        __syncthreads();
    }
    if (tid == 0) g_zpart[bid] = zred[0];
}

// ---------------------------------------------------------------------------
// Kernel B: blocks [0,256) = top-64 selection per (g,e) -> compact g_top
//           blocks [256, 256+2048) = grid-stride zero fill of out.
// No race: selection writes only scratch, memset writes only out.
// ---------------------------------------------------------------------------
__global__ __launch_bounds__(NTHREADS)
void router_zero_sel(float* __restrict__ out)
{
    const int bid = blockIdx.x;
    const int tid = threadIdx.x;

    if (bid >= SEL_BLOCKS) {
        uint4 z; z.x = 0u; z.y = 0u; z.z = 0u; z.w = 0u;
        uint4* o4 = reinterpret_cast<uint4*>(out);
        const size_t n4 = (2*GTEC) / 4;                    // 33,554,432
        size_t i = (size_t)(bid - SEL_BLOCKS) * NTHREADS + tid;
        const size_t stride = (size_t)ZERO_BLOCKS * NTHREADS;
        for (; i < n4; i += stride) o4[i] = z;
        return;
    }

    // ---- selection for (g,e) = bid ----
    const float* row = g_probs + (size_t)bid * T;

    float v[16];
#pragma unroll
    for (int j = 0; j < 16; j++) v[j] = row[tid + j * NTHREADS];

    float bvv = -INFINITY; int bt = tid;
#pragma unroll
    for (int j = 0; j < 16; j++)
        if (v[j] > bvv) { bvv = v[j]; bt = j * NTHREADS + tid; }

    __shared__ float swv[8];
    __shared__ int   swt[8];
    __shared__ int   wint;

    const int lane = tid & 31;
    const int wrp  = tid >> 5;

    for (int c = 0; c < C; c++) {
        float rv = bvv; int rt = bt;
#pragma unroll
        for (int off = 16; off; off >>= 1) {
            float ov = __shfl_xor_sync(0xffffffffu, rv, off);
            int   oi = __shfl_xor_sync(0xffffffffu, rt, off);
            if (ov > rv || (ov == rv && oi < rt)) { rv = ov; rt = oi; }
        }
        if (lane == 0) { swv[wrp] = rv; swt[wrp] = rt; }
        __syncthreads();
        if (tid == 0) {
            float Rv = swv[0]; int Rt = swt[0];
            for (int w = 1; w < 8; w++)
                if (swv[w] > Rv || (swv[w] == Rv && swt[w] < Rt)) {
                    Rv = swv[w]; Rt = swt[w];
                }
            wint = Rt;
            g_topv[bid * C + c] = Rv;
            g_topt[bid * C + c] = Rt;
        }
        __syncthreads();
        const int wt = wint;
        if ((wt & (NTHREADS - 1)) == tid) {
            v[wt >> 8] = -INFINITY;
            bvv = -INFINITY; bt = tid;
#pragma unroll
            for (int j = 0; j < 16; j++)
                if (v[j] > bvv) { bvv = v[j]; bt = j * NTHREADS + tid; }
        }
    }
}

// ---------------------------------------------------------------------------
// Kernel C: scatter the 16384 winners into combine/dispatch + z-loss finalize.
// ---------------------------------------------------------------------------
__global__ __launch_bounds__(NTHREADS)
void router_scatter(float* __restrict__ out)
{
    const int idx = blockIdx.x * NTHREADS + threadIdx.x;   // [0, 16384)

    if (idx == 0) {
        float s = 0.f;
        for (int i = 0; i < GEMM_BLOCKS; i++) s += g_zpart[i];
        out[2 * GTEC] = s / (float)GT;
    }

    const int ge = idx >> 6;          // (g,e) pair
    const int c  = idx & (C - 1);
    const int g  = ge >> 5;
    const int e  = ge & (E - 1);
    const int t  = g_topt[idx];
    const float val = g_topv[idx];

    const size_t off = (((size_t)(g * T + t)) * E + e) * C + c;
    out[off]        = val;            // combine
    out[GTEC + off] = 1.0f;           // dispatch
}

__global__ void nop_k() {}

// ---------------------------------------------------------------------------
extern "C" void kernel_launch(void* const* d_in, const int* in_sizes, int n_in,
                              void* d_out, int out_size)
{
    const float* x  = (const float*)d_in[0];
    const float* Wm = (const float*)d_in[1];
    const float* bv = (const float*)d_in[2];
    float* out = (float*)d_out;

    router_gemm<<<GEMM_BLOCKS, NTHREADS>>>(x, Wm, bv);
    // two pads so ncu (-s 5 -c 1, harness offset 2) captures router_zero_sel
    nop_k<<<1, 32>>>();
    nop_k<<<1, 32>>>();
    router_zero_sel<<<SEL_BLOCKS + ZERO_BLOCKS, NTHREADS>>>(out);
    router_scatter<<<(G * E * C) / NTHREADS, NTHREADS>>>(out);
}

// round 5
// speedup vs baseline: 1.8463x; 1.0173x over previous
#include <cuda_runtime.h>
#include <cstdint>
#include <math.h>

// Problem constants
#define G  8
#define T  4096
#define H  1024
#define E  32
#define C  64
#define GT (G*T)                       // 32768 tokens
#define GTEC ((size_t)G*(size_t)T*(size_t)E*(size_t)C)   // 67,108,864

// GEMM tiling: 128 tokens per block, 128 threads, 256 blocks
#define MTILE 128
#define KTILE 32
#define NKC   (H/KTILE)                // 32 k-chunks
#define XP    (MTILE+1)                // padded xs row
#define GEMM_BLOCKS (GT/MTILE)         // 256
#define GTHREADS 128

#define NTHREADS 256
#define SEL_BLOCKS  (G*E)              // 256
#define ZERO_BLOCKS 2048

// Scratch (device globals; no allocations allowed)
__device__ float g_probs[G*E*T];       // probs transposed [g][e][t], 4 MB
__device__ float g_zpart[GEMM_BLOCKS];
__device__ float g_topv[G*E*C];        // top-64 values per (g,e)
__device__ int   g_topt[G*E*C];        // top-64 token ids per (g,e)

// ---------------------------------------------------------------------------
// Kernel A: double-buffered router GEMM + softmax + z partials.
// 256 blocks x 128 threads -> ~5 CTAs/SM resident, latency overlapped.
// ---------------------------------------------------------------------------
__global__ __launch_bounds__(GTHREADS)
void router_gemm(const float* __restrict__ x,   // [G,T,H]
                 const float* __restrict__ Wm,  // [H,E]
                 const float* __restrict__ bv)  // [E]
{
    const int bid = blockIdx.x;
    const int tid = threadIdx.x;

    __shared__ __align__(16) float xs[KTILE * XP];   // x tile transposed [k][t]
    __shared__ __align__(16) float ws[KTILE * E];    // W tile [k][e]
    __shared__ float zred[GTHREADS];

    const int gtBase = bid * MTILE;
    const float* xbase = x + (size_t)gtBase * H;

    unsigned long long acc[16];
#pragma unroll
    for (int i = 0; i < 16; i++) acc[i] = 0ull;

    // prefetch: 8 float4 of x + 2 float4 of W per thread
    float4 pfx[8];
    float4 pfw[2];

    // x tile = 128 tokens x 32 k = 1024 float4; 128 threads -> 8 each
    //   s = r*128 + tid ; tl = s>>3 ; k4 = s&7
#pragma unroll
    for (int r = 0; r < 8; r++) {
        int s  = r * GTHREADS + tid;
        int tl = s >> 3;
        int k4 = s & 7;
        pfx[r] = *reinterpret_cast<const float4*>(xbase + (size_t)tl * H + k4 * 4);
    }
    // W tile = 32x32 = 256 float4; 128 threads -> 2 each
#pragma unroll
    for (int r = 0; r < 2; r++)
        pfw[r] = *reinterpret_cast<const float4*>(Wm + (r * GTHREADS + tid) * 4);

    for (int kc = 0; kc < NKC; kc++) {
        __syncthreads();
#pragma unroll
        for (int r = 0; r < 8; r++) {
            int s  = r * GTHREADS + tid;
            int tl = s >> 3;
            int k4 = s & 7;
            xs[(k4 * 4 + 0) * XP + tl] = pfx[r].x;
            xs[(k4 * 4 + 1) * XP + tl] = pfx[r].y;
            xs[(k4 * 4 + 2) * XP + tl] = pfx[r].z;
            xs[(k4 * 4 + 3) * XP + tl] = pfx[r].w;
        }
#pragma unroll
        for (int r = 0; r < 2; r++)
            *reinterpret_cast<float4*>(ws + (r * GTHREADS + tid) * 4) = pfw[r];
        __syncthreads();

        if (kc + 1 < NKC) {
            const float* xn = xbase + (kc + 1) * KTILE;
#pragma unroll
            for (int r = 0; r < 8; r++) {
                int s  = r * GTHREADS + tid;
                int tl = s >> 3;
                int k4 = s & 7;
                pfx[r] = *reinterpret_cast<const float4*>(xn + (size_t)tl * H + k4 * 4);
            }
            const float* wn = Wm + (kc + 1) * KTILE * E;
#pragma unroll
            for (int r = 0; r < 2; r++)
                pfw[r] = *reinterpret_cast<const float4*>(wn + (r * GTHREADS + tid) * 4);
        }

#pragma unroll
        for (int kk = 0; kk < KTILE; kk++) {
            const float xv = xs[kk * XP + tid];
            unsigned long long xx;
            asm("mov.b64 %0, {%1,%1};" : "=l"(xx) : "r"(__float_as_uint(xv)));
            const ulonglong2* wr = reinterpret_cast<const ulonglong2*>(ws + kk * E);
#pragma unroll
            for (int q = 0; q < 8; q++) {
                ulonglong2 wp = wr[q];
                asm("fma.rn.f32x2 %0, %1, %2, %0;"
                    : "+l"(acc[2*q])   : "l"(xx), "l"(wp.x));
                asm("fma.rn.f32x2 %0, %1, %2, %0;"
                    : "+l"(acc[2*q+1]) : "l"(xx), "l"(wp.y));
            }
        }
    }

    // ---- epilogue: bias, softmax, transposed prob write, z partial ----
    float l[E];
#pragma unroll
    for (int i = 0; i < 16; i++) {
        float2 f = *reinterpret_cast<float2*>(&acc[i]);
        l[2*i]   = f.x;
        l[2*i+1] = f.y;
    }
#pragma unroll
    for (int e = 0; e < E; e++) l[e] += __ldg(&bv[e]);

    float m = l[0];
#pragma unroll
    for (int e = 1; e < E; e++) m = fmaxf(m, l[e]);
    float s = 0.f;
#pragma unroll
    for (int e = 0; e < E; e++) { l[e] = expf(l[e] - m); s += l[e]; }
    const float inv = 1.f / s;

    const int token = gtBase + tid;
    const int g  = token >> 12;
    const int tt = token & (T - 1);
    float* pr = g_probs + (size_t)g * E * T + tt;
#pragma unroll
    for (int e = 0; e < E; e++) pr[(size_t)e * T] = l[e] * inv;

    const float lse = m + logf(s);
    zred[tid] = lse * lse;
    __syncthreads();
    for (int st = GTHREADS / 2; st > 0; st >>= 1) {
        if (tid < st) zred[tid] += zred[tid + st];
        __syncthreads();
    }
    if (tid == 0) g_zpart[bid] = zred[0];
}

// ---------------------------------------------------------------------------
// Kernel B: blocks [0,256) = top-64 selection per (g,e) -> compact g_top
//           blocks [256, 256+2048) = grid-stride streaming zero fill of out.
// ---------------------------------------------------------------------------
__global__ __launch_bounds__(NTHREADS)
void router_zero_sel(float* __restrict__ out)
{
    const int bid = blockIdx.x;
    const int tid = threadIdx.x;

    if (bid >= SEL_BLOCKS) {
        uint4 z; z.x = 0u; z.y = 0u; z.z = 0u; z.w = 0u;
        uint4* o4 = reinterpret_cast<uint4*>(out);
        const size_t n4 = (2*GTEC) / 4;                    // 33,554,432
        size_t i = (size_t)(bid - SEL_BLOCKS) * NTHREADS + tid;
        const size_t stride = (size_t)ZERO_BLOCKS * NTHREADS;
        for (; i < n4; i += stride) __stcs(o4 + i, z);     // evict-streaming
        return;
    }

    // ---- selection for (g,e) = bid ----
    const float* row = g_probs + (size_t)bid * T;

    float v[16];
#pragma unroll
    for (int j = 0; j < 16; j++) v[j] = row[tid + j * NTHREADS];

    float bvv = -INFINITY; int bt = tid;
#pragma unroll
    for (int j = 0; j < 16; j++)
        if (v[j] > bvv) { bvv = v[j]; bt = j * NTHREADS + tid; }

    __shared__ float swv[8];
    __shared__ int   swt[8];
    __shared__ int   wint;

    const int lane = tid & 31;
    const int wrp  = tid >> 5;

    for (int c = 0; c < C; c++) {
        float rv = bvv; int rt = bt;
#pragma unroll
        for (int off = 16; off; off >>= 1) {
            float ov = __shfl_xor_sync(0xffffffffu, rv, off);
            int   oi = __shfl_xor_sync(0xffffffffu, rt, off);
            if (ov > rv || (ov == rv && oi < rt)) { rv = ov; rt = oi; }
        }
        if (lane == 0) { swv[wrp] = rv; swt[wrp] = rt; }
        __syncthreads();
        if (tid == 0) {
            float Rv = swv[0]; int Rt = swt[0];
            for (int w = 1; w < 8; w++)
                if (swv[w] > Rv || (swv[w] == Rv && swt[w] < Rt)) {
                    Rv = swv[w]; Rt = swt[w];
                }
            wint = Rt;
            g_topv[bid * C + c] = Rv;
            g_topt[bid * C + c] = Rt;
        }
        __syncthreads();
        const int wt = wint;
        if ((wt & (NTHREADS - 1)) == tid) {
            v[wt >> 8] = -INFINITY;
            bvv = -INFINITY; bt = tid;
#pragma unroll
            for (int j = 0; j < 16; j++)
                if (v[j] > bvv) { bvv = v[j]; bt = j * NTHREADS + tid; }
        }
    }
}

// ---------------------------------------------------------------------------
// Kernel C: scatter the 16384 winners into combine/dispatch + z-loss finalize.
// ---------------------------------------------------------------------------
__global__ __launch_bounds__(NTHREADS)
void router_scatter(float* __restrict__ out)
{
    const int idx = blockIdx.x * NTHREADS + threadIdx.x;   // [0, 16384)

    if (idx == 0) {
        float s = 0.f;
        for (int i = 0; i < GEMM_BLOCKS; i++) s += g_zpart[i];
        out[2 * GTEC] = s / (float)GT;
    }

    const int ge = idx >> 6;          // (g,e) pair
    const int c  = idx & (C - 1);
    const int g  = ge >> 5;
    const int e  = ge & (E - 1);
    const int t  = g_topt[idx];
    const float val = g_topv[idx];

    const size_t off = (((size_t)(g * T + t)) * E + e) * C + c;
    out[off]        = val;            // combine
    out[GTEC + off] = 1.0f;           // dispatch
}

__global__ void nop_k() {}

// ---------------------------------------------------------------------------
extern "C" void kernel_launch(void* const* d_in, const int* in_sizes, int n_in,
                              void* d_out, int out_size)
{
    const float* x  = (const float*)d_in[0];
    const float* Wm = (const float*)d_in[1];
    const float* bv = (const float*)d_in[2];
    float* out = (float*)d_out;

    // harness launches 2 first; 3 nops put router_gemm at global idx 5 for ncu
    nop_k<<<1, 32>>>();
    nop_k<<<1, 32>>>();
    nop_k<<<1, 32>>>();
    router_gemm<<<GEMM_BLOCKS, GTHREADS>>>(x, Wm, bv);
    router_zero_sel<<<SEL_BLOCKS + ZERO_BLOCKS, NTHREADS>>>(out);
    router_scatter<<<(G * E * C) / NTHREADS, NTHREADS>>>(out);
}